// round 3
// baseline (speedup 1.0000x reference)
#include <cuda_runtime.h>
#include <cstdint>

typedef unsigned long long u64;

#define NQ      12
#define THREADS 256
#define BATCH   4096
#define FEAT    768
#define NCLASS  10
#define DEPTH   3

// dynamic smem layout (bytes)
#define OFF_BX0   0
#define OFF_BY0   16384
#define OFF_BX1   32768
#define OFF_BY1   49152
#define OFF_ROTP  65536              // u64 [36][8]  = 2304
#define OFF_ROTS  (OFF_ROTP + 2304)  // float [36][4] = 576
#define OFF_CS    (OFF_ROTS + 576)   // float2 [12]   = 96
#define OFF_RED   (OFF_CS   + 96)    // float [8][12] = 384
#define SMEM_BYTES (OFF_RED + 384)

struct GF2Args {
    int c0col[12];
    int c1col[12];
    int mrow[12];
};

__device__ __forceinline__ u64 f2mul(u64 a, u64 b) {
    u64 d; asm("mul.rn.f32x2 %0,%1,%2;" : "=l"(d) : "l"(a), "l"(b)); return d;
}
__device__ __forceinline__ u64 f2fma(u64 a, u64 b, u64 c) {
    u64 d; asm("fma.rn.f32x2 %0,%1,%2,%3;" : "=l"(d) : "l"(a), "l"(b), "l"(c)); return d;
}
__device__ __forceinline__ u64 packf2(float lo, float hi) {
    u64 d; asm("mov.b64 %0,{%1,%2};" : "=l"(d) : "f"(lo), "f"(hi)); return d;
}
__device__ __forceinline__ void unpackf2(u64 a, float& lo, float& hi) {
    asm("mov.b64 {%0,%1},%2;" : "=f"(lo), "=f"(hi) : "l"(a));
}

// canonical boundary layout: amp with stage-coords (t: 8 thread bits, v: 4 local bits)
// lives at st_x[slot], st_y[slot]. bit0 = v&1 (LDS.64-pairable), conflict-free both sides.
__device__ __forceinline__ int slot_of(int t, int v) {
    return (t << 4) ^ ((((v >> 1) ^ ((t >> 1) & 7))) << 1) ^ (v & 1)
         ^ (((((v >> 3) ^ (t >> 4))) & 1) << 4);
}

// all 4 gates of one stage on the 16 register-resident amps.
// gb = rotm index of the local-bit-0 gate; local bit m uses index gb-m.
__device__ __forceinline__ void do_gates(u64 Px[8], u64 Py[8],
                                         const float (*rS)[4], const u64 (*rP)[8],
                                         int gb) {
    // --- scalar gate on local bit 0 (pair lives inside each packed reg) ---
    {
        const float ur = rS[gb][0], ui = rS[gb][1], vr = rS[gb][2], vi = rS[gb][3];
#pragma unroll
        for (int j = 0; j < 8; ++j) {
            float ax, bx, ay, by;
            unpackf2(Px[j], ax, bx);
            unpackf2(Py[j], ay, by);
            const float hx =  ur * ax - ui * ay + vr * bx - vi * by;
            const float hy =  ui * ax + ur * ay + vi * bx + vr * by;
            const float gx = -vr * ax - vi * ay + ur * bx + ui * by;
            const float gy =  vi * ax - vr * ay - ui * bx + ur * by;
            Px[j] = packf2(hx, gx);
            Py[j] = packf2(hy, gy);
        }
    }
    // --- packed gates on local bits 1..3: pure fma.rn.f32x2, no lane mixing ---
#pragma unroll
    for (int m = 1; m <= 3; ++m) {
        const u64* c = rP[gb - m];
        const u64 c0 = c[0], c1 = c[1], c2 = c[2], c3 = c[3],
                  c4 = c[4], c5 = c[5], c6 = c[6];
        const int mj = 1 << (m - 1);
#pragma unroll
        for (int j = 0; j < 8; ++j) {
            if (j & mj) continue;
            const int ja = j, jb = j | mj;
            const u64 xa = Px[ja], ya = Py[ja], xb = Px[jb], yb = Py[jb];
            Px[ja] = f2fma(c0, xa, f2fma(c2, ya, f2fma(c3, xb, f2mul(c6, yb))));
            Py[ja] = f2fma(c1, xa, f2fma(c0, ya, f2fma(c5, xb, f2mul(c3, yb))));
            Px[jb] = f2fma(c4, xa, f2fma(c6, ya, f2fma(c0, xb, f2mul(c1, yb))));
            Py[jb] = f2fma(c5, xa, f2fma(c4, ya, f2fma(c2, xb, f2mul(c0, yb))));
        }
    }
}

__global__ __launch_bounds__(THREADS, 2)
void qhead_kernel(const float* __restrict__ x,
                  const float* __restrict__ Wp,
                  const float* __restrict__ weights,
                  const float* __restrict__ Wo,
                  const float* __restrict__ bo,
                  float* __restrict__ out,
                  GF2Args g)
{
    extern __shared__ unsigned char smem_raw[];
    float*  bx0 = (float*)(smem_raw + OFF_BX0);
    float*  by0 = (float*)(smem_raw + OFF_BY0);
    float*  bx1 = (float*)(smem_raw + OFF_BX1);
    float*  by1 = (float*)(smem_raw + OFF_BY1);
    u64   (*rP)[8] = (u64 (*)[8])(smem_raw + OFF_ROTP);
    float (*rS)[4] = (float (*)[4])(smem_raw + OFF_ROTS);
    float2* cs = (float2*)(smem_raw + OFF_CS);
    float (*red)[NQ] = (float (*)[NQ])(smem_raw + OFF_RED);

    const int t    = threadIdx.x;
    const int b    = blockIdx.x;
    const int lane = t & 31;
    const int warp = t >> 5;

    // ---- angle encoding: 12 dot products (len 768), tanh, half-angle sincos ----
    {
        const float* xr = x + (size_t)b * FEAT;
        const int q0 = warp;
        const bool two = (warp < 4);
        const float* wp0 = Wp + q0 * FEAT;
        const float* wp1 = Wp + (q0 + 8) * FEAT;
        float d0 = 0.f, d1 = 0.f;
        for (int i = lane; i < FEAT; i += 32) {
            const float xv = xr[i];
            d0 += xv * wp0[i];
            if (two) d1 += xv * wp1[i];
        }
#pragma unroll
        for (int o = 16; o; o >>= 1) {
            d0 += __shfl_xor_sync(0xffffffffu, d0, o);
            d1 += __shfl_xor_sync(0xffffffffu, d1, o);
        }
        if (lane == 0) {
            float th = tanhf(d0) * 0.7853981633974483f;   // theta/2
            float c, s; __sincosf(th, &s, &c);
            cs[q0] = make_float2(c, s);
            if (two) {
                float th1 = tanhf(d1) * 0.7853981633974483f;
                float c1, s1; __sincosf(th1, &s1, &c1);
                cs[q0 + 8] = make_float2(c1, s1);
            }
        }
    }

    // ---- Rot matrices. u = m00 = (ur,ui), v = m01 = (vr,vi); m10 = (-vr,vi), m11 = (ur,-ui) ----
    if (t < 36) {
        const float phi = weights[t * 3 + 0];
        const float th  = weights[t * 3 + 1];
        const float om  = weights[t * 3 + 2];
        float c, s; __sincosf(0.5f * th, &s, &c);
        const float aa = 0.5f * (phi + om);
        const float bb = 0.5f * (phi - om);
        float sa, ca, sb, cb;
        __sincosf(aa, &sa, &ca);
        __sincosf(bb, &sb, &cb);
        const float ur = c * ca, ui = -c * sa;
        const float vr = -s * cb, vi = -s * sb;
        rS[t][0] = ur; rS[t][1] = ui; rS[t][2] = vr; rS[t][3] = vi;
        rP[t][0] = packf2(ur, ur);
        rP[t][1] = packf2(ui, ui);
        rP[t][2] = packf2(-ui, -ui);
        rP[t][3] = packf2(vr, vr);
        rP[t][4] = packf2(-vr, -vr);
        rP[t][5] = packf2(vi, vi);
        rP[t][6] = packf2(-vi, -vi);
        rP[t][7] = 0ull;
    }
    __syncthreads();

    // per-stage load address pieces (same formula all stages: f = slot>>1)
    const int s3 = (t >> 1) & 7;
    const int t4 = (t >> 4) & 1;
    const int fb = (t << 3) ^ s3 ^ (t4 << 3);

    // ---- init product state into buffer 0 (stage-A layout: p = t<<4 | v) ----
    {
        // t bit k <-> p bit 4+k <-> wire 7-k ; v bit m <-> p bit m <-> wire 11-m
        float base = 1.f;
#pragma unroll
        for (int k = 0; k < 8; ++k) {
            const float2 csv = cs[7 - k];
            base *= ((t >> k) & 1) ? csv.y : csv.x;
        }
        const float2 g0 = cs[11], g1 = cs[10], g2 = cs[9], g3 = cs[8];
#pragma unroll
        for (int j = 0; j < 8; ++j) {
            float common = base;
            common *= (j & 1) ? g1.y : g1.x;
            common *= (j & 2) ? g2.y : g2.x;
            common *= (j & 4) ? g3.y : g3.x;
            const int f = fb ^ j ^ (((j >> 2) & 1) << 3);
            *(u64*)(bx0 + 2 * f) = packf2(common * g0.x, common * g0.y);
            *(u64*)(by0 + 2 * f) = 0ull;
        }
    }
    __syncthreads();

    float* cur_x = bx0; float* cur_y = by0;
    float* alt_x = bx1; float* alt_y = by1;

    u64 Px[8], Py[8];

#pragma unroll 1
    for (int l = 0; l < DEPTH; ++l) {
#pragma unroll 1
        for (int s = 0; s < 3; ++s) {
            // ---- load 16 amps (8 packed pairs) from current layout ----
#pragma unroll
            for (int j = 0; j < 8; ++j) {
                const int f = fb ^ j ^ (((j >> 2) & 1) << 3);
                Px[j] = *(const u64*)(cur_x + 2 * f);
                Py[j] = *(const u64*)(cur_y + 2 * f);
            }

            // ---- 4 gates; local bit0 wire = 11-4s ----
            do_gates(Px, Py, rS, rP, l * 12 + (11 - 4 * s));

            const bool last = (l == DEPTH - 1) && (s == 2);
            if (!last) {
                // unpack to 16 scalars
                float xv[16], yv[16];
#pragma unroll
                for (int j = 0; j < 8; ++j) {
                    unpackf2(Px[j], xv[2 * j], xv[2 * j + 1]);
                    unpackf2(Py[j], yv[2 * j], yv[2 * j + 1]);
                }
                if (s == 0) {
                    // A -> B: p = t<<4 | v ; t_B = v | (t>>4)<<4 ; v_B = t&15
                    const int hi = t >> 4, vb = t & 15;
#pragma unroll
                    for (int v = 0; v < 16; ++v) {
                        const int slot = slot_of(v | (hi << 4), vb);
                        alt_x[slot] = xv[v];
                        alt_y[slot] = yv[v];
                    }
                } else if (s == 1) {
                    // B -> C: p = (t&15) | v<<4 | (t>>4)<<8 ; t_C = (t&15)|v<<4 ; v_C = t>>4
                    const int lo4 = t & 15, vc = t >> 4;
#pragma unroll
                    for (int v = 0; v < 16; ++v) {
                        const int slot = slot_of(lo4 | (v << 4), vc);
                        alt_x[slot] = xv[v];
                        alt_y[slot] = yv[v];
                    }
                } else {
                    // C -> A of next layer, through the free CNOT relabeling:
                    // p = t | v<<8 ; dst = C*p ; store at stage-A layout of dst
                    const int* col = (l == 0) ? g.c0col : g.c1col;
                    int dT = 0;
#pragma unroll
                    for (int j = 0; j < 8; ++j) dT ^= ((t >> j) & 1) ? col[j] : 0;
                    const int c8 = col[8], c9 = col[9], c10 = col[10], c11 = col[11];
#pragma unroll
                    for (int v = 0; v < 16; ++v) {
                        const int dst = dT ^ ((v & 1) ? c8 : 0) ^ ((v & 2) ? c9 : 0)
                                           ^ ((v & 4) ? c10 : 0) ^ ((v & 8) ? c11 : 0);
                        const int slot = slot_of(dst >> 4, dst & 15);
                        alt_x[slot] = xv[v];
                        alt_y[slot] = yv[v];
                    }
                }
                __syncthreads();
                float* tx = cur_x; cur_x = alt_x; alt_x = tx;
                float* ty = cur_y; cur_y = alt_y; alt_y = ty;
            }
        }
    }

    // ---- measurement: amps are stage-C regs, p = t | v<<8 ; final-layer CNOTs
    //      folded into parity masks mrow ----
    float pv[16];
#pragma unroll
    for (int j = 0; j < 8; ++j) {
        const u64 pp = f2fma(Px[j], Px[j], f2mul(Py[j], Py[j]));
        unpackf2(pp, pv[2 * j], pv[2 * j + 1]);
    }
    unsigned tab[NQ];
#pragma unroll
    for (int q = 0; q < NQ; ++q) {
        const int row = g.mrow[q];
        const int hi = (row >> 8) & 15;
        unsigned tb = 0;
        if (hi & 1) tb ^= 0xAAAAu;
        if (hi & 2) tb ^= 0xCCCCu;
        if (hi & 4) tb ^= 0xF0F0u;
        if (hi & 8) tb ^= 0xFF00u;
        if (__popc(row & t) & 1) tb = ~tb;
        tab[q] = tb;
    }
    float acc[NQ];
#pragma unroll
    for (int q = 0; q < NQ; ++q) acc[q] = 0.f;
#pragma unroll
    for (int v = 0; v < 16; ++v) {
        const float p = pv[v], np = -pv[v];
#pragma unroll
        for (int q = 0; q < NQ; ++q)
            acc[q] += ((tab[q] >> v) & 1) ? np : p;
    }
#pragma unroll
    for (int q = 0; q < NQ; ++q) {
        float vq = acc[q];
#pragma unroll
        for (int o = 16; o; o >>= 1) vq += __shfl_xor_sync(0xffffffffu, vq, o);
        if (lane == 0) red[warp][q] = vq;
    }
    __syncthreads();

    // ---- output head ----
    if (t < NCLASS) {
        float o = bo[t];
#pragma unroll
        for (int q = 0; q < NQ; ++q) {
            float z = 0.f;
#pragma unroll
            for (int w = 0; w < 8; ++w) z += red[w][q];
            o += z * Wo[t * NQ + q];
        }
        out[(size_t)b * NCLASS + t] = o;
    }
}

// ---- host: GF(2) composites of the fixed CNOT rings (r = 1,2,3) ----
static void build_gf2(GF2Args& a) {
    int rows[12], cols[12];
    for (int l = 0; l < 3; ++l) {
        for (int j = 0; j < 12; ++j) { rows[j] = 1 << j; cols[j] = 1 << j; }
        const int r = l % 11 + 1;
        for (int q = 0; q < 12; ++q) {
            const int c = q, tg = (q + r) % 12;
            const int bc = 11 - c, bt = 11 - tg;
            rows[bt] ^= rows[bc];
            for (int j = 0; j < 12; ++j)
                if ((cols[j] >> bc) & 1) cols[j] ^= (1 << bt);
        }
        if (l == 0) for (int j = 0; j < 12; ++j) a.c0col[j] = cols[j];
        if (l == 1) for (int j = 0; j < 12; ++j) a.c1col[j] = cols[j];
        if (l == 2) for (int q = 0; q < 12; ++q) a.mrow[q] = rows[11 - q];
    }
}

extern "C" void kernel_launch(void* const* d_in, const int* in_sizes, int n_in,
                              void* d_out, int out_size) {
    (void)in_sizes; (void)n_in; (void)out_size;
    const float* x       = (const float*)d_in[0];
    const float* Wp      = (const float*)d_in[1];
    const float* weights = (const float*)d_in[2];
    const float* Wo      = (const float*)d_in[3];
    const float* bo      = (const float*)d_in[4];

    static int attr_done = 0;
    if (!attr_done) {
        cudaFuncSetAttribute(qhead_kernel,
                             cudaFuncAttributeMaxDynamicSharedMemorySize, SMEM_BYTES);
        attr_done = 1;
    }

    GF2Args g;
    build_gf2(g);

    qhead_kernel<<<BATCH, THREADS, SMEM_BYTES>>>(x, Wp, weights, Wo, bo,
                                                 (float*)d_out, g);
}

// round 4
// speedup vs baseline: 1.2983x; 1.2983x over previous
#include <cuda_runtime.h>
#include <cstdint>

#define NQ      12
#define DIM     4096      // 2^12 amplitudes
#define THREADS 256
#define BATCH   4096
#define FEAT    768
#define NCLASS  10

// GF(2) bookkeeping for the (compile-time-fixed) CNOT ring structure.
// c0col: columns of layer-0 CNOT composite (folded into the init scatter)
// c1col: columns of layer-1 composite (mid-loop scatter)
// mrow[q]: row (11-q) of layer-2 composite (measurement parity mask per wire)
struct GF2Args {
    int c0col[12];
    int c1col[12];
    int mrow[12];
};

// apply 4 complex 2x2 gates (local bits 0..3 of the 16-amp register block)
template <int STAGE>
__device__ __forceinline__ void apply4(float2 amp[16], const float (&rotm)[36][8], int l) {
#pragma unroll
    for (int g = 0; g < 4; ++g) {
        const int wire = 11 - (STAGE * 4 + g);
        const float* m = rotm[l * 12 + wire];
        const float m00r = m[0], m00i = m[1], m01r = m[2], m01i = m[3];
        const float m10r = m[4], m10i = m[5], m11r = m[6], m11i = m[7];
        const int mask = 1 << g;
#pragma unroll
        for (int k = 0; k < 8; ++k) {
            const int h  = ((k & ~(mask - 1)) << 1) | (k & (mask - 1));
            const int h2 = h | mask;
            const float2 a = amp[h], b = amp[h2];
            amp[h].x  = m00r * a.x - m00i * a.y + m01r * b.x - m01i * b.y;
            amp[h].y  = m00r * a.y + m00i * a.x + m01r * b.y + m01i * b.x;
            amp[h2].x = m10r * a.x - m10i * a.y + m11r * b.x - m11i * b.y;
            amp[h2].y = m10r * a.y + m10i * a.x + m11r * b.y + m11i * b.x;
        }
    }
}

__global__ __launch_bounds__(THREADS)
void qhead_kernel(const float* __restrict__ x,
                  const float* __restrict__ Wp,
                  const float* __restrict__ weights,
                  const float* __restrict__ Wo,
                  const float* __restrict__ bo,
                  float* __restrict__ out,
                  GF2Args g)
{
    __shared__ float2 st[DIM];          // swizzled state: slot(p) = p ^ ((p>>4)&15)
    __shared__ float2 cs[NQ];           // (cos(th/2), sin(th/2)) per wire
    __shared__ float  rotm[36][8];      // 36 Rot matrices (complex 2x2)
    __shared__ float4 Fm[NQ];           // merged per-wire factor Rot0 * RY(a) |0>
    __shared__ float  red[8][NQ];       // cross-warp reduction buffer

    const int t    = threadIdx.x;
    const int b    = blockIdx.x;
    const int lane = t & 31;
    const int warp = t >> 5;

    // ---- angle encoding: 12 dot products of length 768, tanh, half-angle sincos ----
    {
        const float* xr = x + (size_t)b * FEAT;
        const int q0 = warp;
        const bool two = (warp < 4);
        const float* wp0 = Wp + q0 * FEAT;
        const float* wp1 = Wp + (q0 + 8) * FEAT;
        float d0 = 0.f, d1 = 0.f;
        for (int i = lane; i < FEAT; i += 32) {
            const float xv = xr[i];
            d0 += xv * wp0[i];
            if (two) d1 += xv * wp1[i];
        }
#pragma unroll
        for (int o = 16; o; o >>= 1) {
            d0 += __shfl_xor_sync(0xffffffffu, d0, o);
            d1 += __shfl_xor_sync(0xffffffffu, d1, o);
        }
        if (lane == 0) {
            float th = tanhf(d0) * 0.7853981633974483f;   // theta/2
            float c, s; __sincosf(th, &s, &c);
            cs[q0] = make_float2(c, s);
            if (two) {
                float th1 = tanhf(d1) * 0.7853981633974483f;
                float c1, s1; __sincosf(th1, &s1, &c1);
                cs[q0 + 8] = make_float2(c1, s1);
            }
        }
    }

    // ---- Rot matrices: Rot(phi,theta,omega) = RZ(om) RY(th) RZ(phi) ----
    if (t < 36) {
        const float phi = weights[t * 3 + 0];
        const float th  = weights[t * 3 + 1];
        const float om  = weights[t * 3 + 2];
        float c, s; __sincosf(0.5f * th, &s, &c);
        const float aa = 0.5f * (phi + om);
        const float bb = 0.5f * (phi - om);
        float sa, ca, sb, cb;
        __sincosf(aa, &sa, &ca);
        __sincosf(bb, &sb, &cb);
        rotm[t][0] =  c * ca;  rotm[t][1] = -c * sa;   // m00 = e^{-i a} c
        rotm[t][2] = -s * cb;  rotm[t][3] = -s * sb;   // m01 = -e^{+i b} s
        rotm[t][4] =  s * cb;  rotm[t][5] = -s * sb;   // m10 =  e^{-i b} s
        rotm[t][6] =  c * ca;  rotm[t][7] =  c * sa;   // m11 = e^{+i a} c
    }
    __syncthreads();

    // ---- merged per-wire factor: F = Rot0_q * (cos, sin)^T  (c,s real) ----
    if (t < NQ) {
        const float c = cs[t].x, s = cs[t].y;
        const float* m = rotm[t];
        Fm[t] = make_float4(m[0] * c + m[2] * s,   // F0.re
                            m[1] * c + m[3] * s,   // F0.im
                            m[4] * c + m[6] * s,   // F1.re
                            m[5] * c + m[7] * s);  // F1.im
    }
    __syncthreads();

    // ---- init: post-layer0 product state, scattered through layer-0 CNOT ring ----
    // p = t<<4 | v ; p bit j <-> wire 11-j  (t bit k <-> wire 7-k, v bit m <-> wire 11-m)
    {
        float br, bi;
        {
            const float4 f = Fm[7];
            br = (t & 1) ? f.z : f.x;
            bi = (t & 1) ? f.w : f.y;
        }
#pragma unroll
        for (int k = 1; k < 8; ++k) {
            const float4 f = Fm[7 - k];
            const float fr = ((t >> k) & 1) ? f.z : f.x;
            const float fi = ((t >> k) & 1) ? f.w : f.y;
            const float nbr = br * fr - bi * fi;
            bi = br * fi + bi * fr;
            br = nbr;
        }
        // lo: wires 11 (v bit0), 10 (v bit1) ; hi: wires 9 (v bit2), 8 (v bit3)
        float lr[4], li[4], hr[4], hi4[4];
        {
            const float4 fA = Fm[11], fB = Fm[10], fC = Fm[9], fD = Fm[8];
#pragma unroll
            for (int j = 0; j < 4; ++j) {
                const float ar = (j & 1) ? fA.z : fA.x, ai = (j & 1) ? fA.w : fA.y;
                const float br2 = (j & 2) ? fB.z : fB.x, bi2 = (j & 2) ? fB.w : fB.y;
                lr[j] = ar * br2 - ai * bi2;
                li[j] = ar * bi2 + ai * br2;
                const float cr = (j & 1) ? fC.z : fC.x, ci = (j & 1) ? fC.w : fC.y;
                const float dr = (j & 2) ? fD.z : fD.x, di = (j & 2) ? fD.w : fD.y;
                hr[j] = cr * dr - ci * di;
                hi4[j] = cr * di + ci * dr;
            }
        }
        // scatter destination: dst = C0 * p
        int dT = 0;
#pragma unroll
        for (int k = 0; k < 8; ++k) dT ^= ((t >> k) & 1) ? g.c0col[4 + k] : 0;
        const int c0 = g.c0col[0], c1 = g.c0col[1], c2 = g.c0col[2], c3 = g.c0col[3];
#pragma unroll
        for (int v = 0; v < 16; ++v) {
            const float plr = lr[v & 3], pli = li[v & 3];
            const float phr = hr[v >> 2], phi2 = hi4[v >> 2];
            const float tr = plr * phr - pli * phi2;
            const float ti = plr * phi2 + pli * phr;
            const float ar = br * tr - bi * ti;
            const float ai = br * ti + bi * tr;
            const int dst = dT ^ ((v & 1) ? c0 : 0) ^ ((v & 2) ? c1 : 0)
                               ^ ((v & 4) ? c2 : 0) ^ ((v & 8) ? c3 : 0);
            st[dst ^ ((dst >> 4) & 15)] = make_float2(ar, ai);
        }
    }
    __syncthreads();

    float2 amp[16];

    // ---- layers 1 and 2 only (layer 0 folded into init) ----
#pragma unroll 1
    for (int l = 1; l < 3; ++l) {
        // ---- stage A: bits 0-3 (wires 11..8). slot = t*16 + (v ^ (t&15)) ----
        {
            const int base = t * 16, x4 = t & 15;
#pragma unroll
            for (int v = 0; v < 16; ++v) amp[v] = st[base + (v ^ x4)];
            apply4<0>(amp, rotm, l);
#pragma unroll
            for (int v = 0; v < 16; ++v) st[base + (v ^ x4)] = amp[v];
        }
        __syncthreads();

        // ---- stage B: bits 4-7 (wires 7..4). slot = (t>>4)*256 + v*16 + ((t&15)^v) ----
        {
            const int hi = (t >> 4) * 256, x4 = t & 15;
#pragma unroll
            for (int v = 0; v < 16; ++v) amp[v] = st[hi + v * 16 + (x4 ^ v)];
            apply4<1>(amp, rotm, l);
#pragma unroll
            for (int v = 0; v < 16; ++v) st[hi + v * 16 + (x4 ^ v)] = amp[v];
        }
        __syncthreads();

        // ---- stage C: bits 8-11 (wires 3..0). slot = v*256 + (t ^ (t>>4)) ----
        {
            const int slo = t ^ (t >> 4);
#pragma unroll
            for (int v = 0; v < 16; ++v) amp[v] = st[v * 256 + slo];
            apply4<2>(amp, rotm, l);
            if (l == 1) {
                // layer-1 CNOT ring as a free relabeling: scatter new[C*y] = cur[y]
                __syncthreads();
                int dT = 0;
#pragma unroll
                for (int j = 0; j < 8; ++j) dT ^= ((t >> j) & 1) ? g.c1col[j] : 0;
                const int c8 = g.c1col[8], c9 = g.c1col[9],
                          c10 = g.c1col[10], c11 = g.c1col[11];
#pragma unroll
                for (int v = 0; v < 16; ++v) {
                    int dst = dT ^ ((v & 1) ? c8 : 0) ^ ((v & 2) ? c9 : 0)
                                 ^ ((v & 4) ? c10 : 0) ^ ((v & 8) ? c11 : 0);
                    st[dst ^ ((dst >> 4) & 15)] = amp[v];
                }
                __syncthreads();
            }
            // l == 2: keep amps in registers for measurement (final CNOTs folded
            // into the measurement parity masks)
        }
    }

    // ---- PauliZ expectations (amps at p = v*256 + t, logical bit via GF(2) parity) ----
    float acc[NQ];
#pragma unroll
    for (int q = 0; q < NQ; ++q) acc[q] = 0.f;
    unsigned tab[NQ];
#pragma unroll
    for (int q = 0; q < NQ; ++q) {
        const int row = g.mrow[q];
        const int hi = (row >> 8) & 15;
        unsigned tb = 0;
        if (hi & 1) tb ^= 0xAAAAu;
        if (hi & 2) tb ^= 0xCCCCu;
        if (hi & 4) tb ^= 0xF0F0u;
        if (hi & 8) tb ^= 0xFF00u;
        if (__popc(row & t) & 1) tb = ~tb;
        tab[q] = tb;
    }
#pragma unroll
    for (int v = 0; v < 16; ++v) {
        const float2 a = amp[v];
        const float p  = a.x * a.x + a.y * a.y;
        const float np = -p;
#pragma unroll
        for (int q = 0; q < NQ; ++q)
            acc[q] += ((tab[q] >> v) & 1) ? np : p;
    }
#pragma unroll
    for (int q = 0; q < NQ; ++q) {
        float vq = acc[q];
#pragma unroll
        for (int o = 16; o; o >>= 1) vq += __shfl_xor_sync(0xffffffffu, vq, o);
        if (lane == 0) red[warp][q] = vq;
    }
    __syncthreads();

    // ---- output head: out[b][c] = bo[c] + sum_q z[q] * Wo[c][q] ----
    if (t < NCLASS) {
        float o = bo[t];
#pragma unroll
        for (int q = 0; q < NQ; ++q) {
            float z = 0.f;
#pragma unroll
            for (int w = 0; w < 8; ++w) z += red[w][q];
            o += z * Wo[t * NQ + q];
        }
        out[(size_t)b * NCLASS + t] = o;
    }
}

// ---- host: build GF(2) composites of the fixed CNOT rings (r = 1,2,3) ----
static void build_gf2(GF2Args& a) {
    int rows[12], cols[12];
    for (int l = 0; l < 3; ++l) {
        for (int j = 0; j < 12; ++j) { rows[j] = 1 << j; cols[j] = 1 << j; }
        const int r = l % 11 + 1;
        for (int q = 0; q < 12; ++q) {
            const int c = q, tg = (q + r) % 12;
            const int bc = 11 - c, bt = 11 - tg;
            rows[bt] ^= rows[bc];                         // comp <- E * comp (rows)
            for (int j = 0; j < 12; ++j)                  // columns of E * comp
                if ((cols[j] >> bc) & 1) cols[j] ^= (1 << bt);
        }
        if (l == 0) for (int j = 0; j < 12; ++j) a.c0col[j] = cols[j];
        if (l == 1) for (int j = 0; j < 12; ++j) a.c1col[j] = cols[j];
        if (l == 2) for (int q = 0; q < 12; ++q) a.mrow[q] = rows[11 - q];
    }
}

extern "C" void kernel_launch(void* const* d_in, const int* in_sizes, int n_in,
                              void* d_out, int out_size) {
    (void)in_sizes; (void)n_in; (void)out_size;
    const float* x       = (const float*)d_in[0];
    const float* Wp      = (const float*)d_in[1];
    const float* weights = (const float*)d_in[2];
    const float* Wo      = (const float*)d_in[3];
    const float* bo      = (const float*)d_in[4];

    GF2Args g;
    build_gf2(g);

    qhead_kernel<<<BATCH, THREADS>>>(x, Wp, weights, Wo, bo, (float*)d_out, g);
}

// round 5
// speedup vs baseline: 1.5329x; 1.1807x over previous
#include <cuda_runtime.h>
#include <cstdint>

#define NQ      12
#define DIM     4096      // 2^12 amplitudes
#define THREADS 256
#define BATCH   4096
#define FEAT    768
#define NCLASS  10

// ---- compile-time GF(2) composites of the fixed CNOT rings (hand-derived,
//      verified by basis-state simulation of each ring) ----
// layer-0 composite columns (dst = C0 * p), p bit j <-> wire 11-j
// c0col[0..3] (v bits) folded+swizzled into SLOTK0; c0col[4..11] (t bits) below:
__device__ __constant__ const int C0T[8] = {0x81F,0x83F,0x87F,0x8FF,0x9FF,0xBFF,0xFFF,0x7FF};
static __device__ __constant__ const int SLOTK0[16] = {
    0x000,0x801,0x803,0x002,0x807,0x006,0x004,0x805,
    0x80F,0x00E,0x00C,0x80D,0x008,0x809,0x80B,0x00A};
// layer-1 composite: c1col[0..7] (t bits) and swizzled v-bit combos:
__device__ __constant__ const int C1T[8] = {0x401,0x802,0x405,0x80A,0x415,0x82A,0x455,0x8AA};
static __device__ __constant__ const int SLOTK1[16] = {
    0x000,0x550,0xAA0,0xFF0,0x150,0x400,0xBF0,0xEA0,
    0x2A0,0x7F0,0x800,0xD50,0x3F0,0x6A0,0x950,0xC00};
// layer-2 measurement masks mrow[q] = {0x124,0x92,0x49,0x900,0x480,0x240,
//   0x920,0x490,0x248,0x924,0x492,0x249} -> only Walsh coeffs {0,1,2,4,9} needed.

// apply 4 complex 2x2 gates (local bits 0..3 of the 16-amp register block)
template <int STAGE>
__device__ __forceinline__ void apply4(float2 amp[16], const float (&rotm)[36][8], int l) {
#pragma unroll
    for (int g = 0; g < 4; ++g) {
        const int wire = 11 - (STAGE * 4 + g);
        const float* m = rotm[l * 12 + wire];
        const float m00r = m[0], m00i = m[1], m01r = m[2], m01i = m[3];
        const float m10r = m[4], m10i = m[5], m11r = m[6], m11i = m[7];
        const int mask = 1 << g;
#pragma unroll
        for (int k = 0; k < 8; ++k) {
            const int h  = ((k & ~(mask - 1)) << 1) | (k & (mask - 1));
            const int h2 = h | mask;
            const float2 a = amp[h], b = amp[h2];
            amp[h].x  = m00r * a.x - m00i * a.y + m01r * b.x - m01i * b.y;
            amp[h].y  = m00r * a.y + m00i * a.x + m01r * b.y + m01i * b.x;
            amp[h2].x = m10r * a.x - m10i * a.y + m11r * b.x - m11i * b.y;
            amp[h2].y = m10r * a.y + m10i * a.x + m11r * b.y + m11i * b.x;
        }
    }
}

__global__ __launch_bounds__(THREADS)
void qhead_kernel(const float* __restrict__ x,
                  const float* __restrict__ Wp,
                  const float* __restrict__ weights,
                  const float* __restrict__ Wo,
                  const float* __restrict__ bo,
                  float* __restrict__ out)
{
    __shared__ float2 st[DIM];          // swizzled state: slot(p) = p ^ ((p>>4)&15)
    __shared__ float2 cs[NQ];           // (cos(th/2), sin(th/2)) per wire
    __shared__ float  rotm[36][8];      // 36 Rot matrices (complex 2x2)
    __shared__ float4 Fm[NQ];           // merged per-wire factor Rot0 * RY(a) |0>
    __shared__ float  red[8][NQ];       // cross-warp reduction buffer

    const int t    = threadIdx.x;
    const int b    = blockIdx.x;
    const int lane = t & 31;
    const int warp = t >> 5;

    // ---- angle encoding: 12 dot products (float4), tanh, half-angle sincos ----
    {
        const float4* xr4  = (const float4*)(x + (size_t)b * FEAT);
        const int q0 = warp;
        const bool two = (warp < 4);
        const float4* wp04 = (const float4*)(Wp + q0 * FEAT);
        const float4* wp14 = (const float4*)(Wp + (q0 + 8) * FEAT);
        float d0 = 0.f, d1 = 0.f;
#pragma unroll
        for (int i = lane; i < FEAT / 4; i += 32) {
            const float4 xv = xr4[i];
            const float4 a  = wp04[i];
            d0 += xv.x * a.x + xv.y * a.y + xv.z * a.z + xv.w * a.w;
            if (two) {
                const float4 c = wp14[i];
                d1 += xv.x * c.x + xv.y * c.y + xv.z * c.z + xv.w * c.w;
            }
        }
#pragma unroll
        for (int o = 16; o; o >>= 1) {
            d0 += __shfl_xor_sync(0xffffffffu, d0, o);
            d1 += __shfl_xor_sync(0xffffffffu, d1, o);
        }
        if (lane == 0) {
            float th = tanhf(d0) * 0.7853981633974483f;   // theta/2
            float c, s; __sincosf(th, &s, &c);
            cs[q0] = make_float2(c, s);
            if (two) {
                float th1 = tanhf(d1) * 0.7853981633974483f;
                float c1, s1; __sincosf(th1, &s1, &c1);
                cs[q0 + 8] = make_float2(c1, s1);
            }
        }
    }

    // ---- Rot matrices: Rot(phi,theta,omega) = RZ(om) RY(th) RZ(phi) ----
    if (t < 36) {
        const float phi = weights[t * 3 + 0];
        const float th  = weights[t * 3 + 1];
        const float om  = weights[t * 3 + 2];
        float c, s; __sincosf(0.5f * th, &s, &c);
        const float aa = 0.5f * (phi + om);
        const float bb = 0.5f * (phi - om);
        float sa, ca, sb, cb;
        __sincosf(aa, &sa, &ca);
        __sincosf(bb, &sb, &cb);
        rotm[t][0] =  c * ca;  rotm[t][1] = -c * sa;   // m00 = e^{-i a} c
        rotm[t][2] = -s * cb;  rotm[t][3] = -s * sb;   // m01 = -e^{+i b} s
        rotm[t][4] =  s * cb;  rotm[t][5] = -s * sb;   // m10 =  e^{-i b} s
        rotm[t][6] =  c * ca;  rotm[t][7] =  c * sa;   // m11 = e^{+i a} c
    }
    __syncthreads();

    // ---- merged per-wire factor: F = Rot0_q * (cos, sin)^T  (c,s real) ----
    if (t < NQ) {
        const float c = cs[t].x, s = cs[t].y;
        const float* m = rotm[t];
        Fm[t] = make_float4(m[0] * c + m[2] * s,   // F0.re
                            m[1] * c + m[3] * s,   // F0.im
                            m[4] * c + m[6] * s,   // F1.re
                            m[5] * c + m[7] * s);  // F1.im
    }
    __syncthreads();

    // ---- init: post-layer0 product state scattered through layer-0 CNOT ring ----
    // p = t<<4 | v ; p bit j <-> wire 11-j
    {
        float br, bi;
        {
            const float4 f = Fm[7];
            br = (t & 1) ? f.z : f.x;
            bi = (t & 1) ? f.w : f.y;
        }
#pragma unroll
        for (int k = 1; k < 8; ++k) {
            const float4 f = Fm[7 - k];
            const float fr = ((t >> k) & 1) ? f.z : f.x;
            const float fi = ((t >> k) & 1) ? f.w : f.y;
            const float nbr = br * fr - bi * fi;
            bi = br * fi + bi * fr;
            br = nbr;
        }
        float lr[4], li[4], hr[4], hi4[4];
        {
            const float4 fA = Fm[11], fB = Fm[10], fC = Fm[9], fD = Fm[8];
#pragma unroll
            for (int j = 0; j < 4; ++j) {
                const float ar = (j & 1) ? fA.z : fA.x, ai = (j & 1) ? fA.w : fA.y;
                const float br2 = (j & 2) ? fB.z : fB.x, bi2 = (j & 2) ? fB.w : fB.y;
                lr[j] = ar * br2 - ai * bi2;
                li[j] = ar * bi2 + ai * br2;
                const float cr = (j & 1) ? fC.z : fC.x, ci = (j & 1) ? fC.w : fC.y;
                const float dr = (j & 2) ? fD.z : fD.x, di = (j & 2) ? fD.w : fD.y;
                hr[j] = cr * dr - ci * di;
                hi4[j] = cr * di + ci * dr;
            }
        }
        // sb0 = slot(C0_t * t), per-v offsets are immediates
        int dT = 0;
#pragma unroll
        for (int k = 0; k < 8; ++k) dT ^= ((t >> k) & 1) ? C0T[k] : 0;
        const int sb0 = dT ^ ((dT >> 4) & 15);
#pragma unroll
        for (int v = 0; v < 16; ++v) {
            const float plr = lr[v & 3], pli = li[v & 3];
            const float phr = hr[v >> 2], phi2 = hi4[v >> 2];
            const float tr = plr * phr - pli * phi2;
            const float ti = plr * phi2 + pli * phr;
            st[sb0 ^ SLOTK0[v]] = make_float2(br * tr - bi * ti, br * ti + bi * tr);
        }
    }
    __syncthreads();

    float2 amp[16];

    // ---- layers 1 and 2 (layer 0 folded into init) ----
#pragma unroll 1
    for (int l = 1; l < 3; ++l) {
        // stage A: bits 0-3 (wires 11..8). slot = t*16 + (v ^ (t&15))
        {
            const int base = t * 16, x4 = t & 15;
#pragma unroll
            for (int v = 0; v < 16; ++v) amp[v] = st[base + (v ^ x4)];
            apply4<0>(amp, rotm, l);
#pragma unroll
            for (int v = 0; v < 16; ++v) st[base + (v ^ x4)] = amp[v];
        }
        __syncthreads();

        // stage B: bits 4-7 (wires 7..4). slot = (t>>4)*256 + v*16 + ((t&15)^v)
        {
            const int hi = (t >> 4) * 256, x4 = t & 15;
#pragma unroll
            for (int v = 0; v < 16; ++v) amp[v] = st[hi + v * 16 + (x4 ^ v)];
            apply4<1>(amp, rotm, l);
#pragma unroll
            for (int v = 0; v < 16; ++v) st[hi + v * 16 + (x4 ^ v)] = amp[v];
        }
        __syncthreads();

        // stage C: bits 8-11 (wires 3..0). slot = v*256 + (t ^ (t>>4))
        {
            const int slo = t ^ (t >> 4);
#pragma unroll
            for (int v = 0; v < 16; ++v) amp[v] = st[v * 256 + slo];
            apply4<2>(amp, rotm, l);
            if (l == 1) {
                // layer-1 CNOT ring: free relabeling via immediate-offset scatter
                __syncthreads();
                int dT = 0;
#pragma unroll
                for (int j = 0; j < 8; ++j) dT ^= ((t >> j) & 1) ? C1T[j] : 0;
                const int sb1 = dT ^ ((dT >> 4) & 15);
#pragma unroll
                for (int v = 0; v < 16; ++v)
                    st[sb1 ^ SLOTK1[v]] = amp[v];
                __syncthreads();
            }
            // l == 2: amps stay in registers; final CNOTs folded into parity masks
        }
    }

    // ---- PauliZ expectations via 5 Walsh coefficients of per-thread probs ----
    float pv[16];
#pragma unroll
    for (int v = 0; v < 16; ++v)
        pv[v] = amp[v].x * amp[v].x + amp[v].y * amp[v].y;

    const float Pe = ((pv[0] + pv[2]) + (pv[4] + pv[6])) + ((pv[8] + pv[10]) + (pv[12] + pv[14]));
    const float Po = ((pv[1] + pv[3]) + (pv[5] + pv[7])) + ((pv[9] + pv[11]) + (pv[13] + pv[15]));
    const float w0 = Pe + Po;                    // mask 0
    const float w1 = Pe - Po;                    // mask 1 (bit0 of v)
    const float A  = ((pv[0] + pv[1]) + (pv[4] + pv[5])) + ((pv[8] + pv[9]) + (pv[12] + pv[13]));
    const float w2 = 2.f * A - w0;               // mask 2 (bit1)
    const float Bb = ((pv[0] + pv[1]) + (pv[2] + pv[3])) + ((pv[8] + pv[9]) + (pv[10] + pv[11]));
    const float w4 = 2.f * Bb - w0;              // mask 4 (bit2)
    const float Cc = ((pv[0] + pv[2]) + (pv[4] + pv[6])) + ((pv[9] + pv[11]) + (pv[13] + pv[15]));
    const float w9 = 2.f * Cc - w0;              // mask 9 (bit0^bit3)

    // single-bit parities of t for the low-byte sign masks
    const int t0 = t & 1, t1 = (t >> 1) & 1, t2 = (t >> 2) & 1, t3 = (t >> 3) & 1;
    const int t4 = (t >> 4) & 1, t5 = (t >> 5) & 1, t6 = (t >> 6) & 1, t7 = (t >> 7) & 1;
    const int s24 = t2 ^ t5;          // 0x24
    const int s92 = t1 ^ t4 ^ t7;     // 0x92
    const int s49 = t0 ^ t3 ^ t6;     // 0x49
    const int s90 = t4 ^ t7;          // 0x90
    const int s48 = t3 ^ t6;          // 0x48

    float acc[NQ];
    acc[0]  = s24 ? -w1 : w1;   // mrow 0x124
    acc[1]  = s92 ? -w0 : w0;   // 0x092
    acc[2]  = s49 ? -w0 : w0;   // 0x049
    acc[3]  = w9;               // 0x900
    acc[4]  = t7  ? -w4 : w4;   // 0x480
    acc[5]  = t6  ? -w2 : w2;   // 0x240
    acc[6]  = t5  ? -w9 : w9;   // 0x920
    acc[7]  = s90 ? -w4 : w4;   // 0x490
    acc[8]  = s48 ? -w2 : w2;   // 0x248
    acc[9]  = s24 ? -w9 : w9;   // 0x924
    acc[10] = s92 ? -w4 : w4;   // 0x492
    acc[11] = s49 ? -w2 : w2;   // 0x249

#pragma unroll
    for (int q = 0; q < NQ; ++q) {
        float vq = acc[q];
#pragma unroll
        for (int o = 16; o; o >>= 1) vq += __shfl_xor_sync(0xffffffffu, vq, o);
        if (lane == 0) red[warp][q] = vq;
    }
    __syncthreads();

    // ---- output head: out[b][c] = bo[c] + sum_q z[q] * Wo[c][q] ----
    if (t < NCLASS) {
        float o = bo[t];
#pragma unroll
        for (int q = 0; q < NQ; ++q) {
            float z = 0.f;
#pragma unroll
            for (int w = 0; w < 8; ++w) z += red[w][q];
            o += z * Wo[t * NQ + q];
        }
        out[(size_t)b * NCLASS + t] = o;
    }
}

extern "C" void kernel_launch(void* const* d_in, const int* in_sizes, int n_in,
                              void* d_out, int out_size) {
    (void)in_sizes; (void)n_in; (void)out_size;
    const float* x       = (const float*)d_in[0];
    const float* Wp      = (const float*)d_in[1];
    const float* weights = (const float*)d_in[2];
    const float* Wo      = (const float*)d_in[3];
    const float* bo      = (const float*)d_in[4];

    qhead_kernel<<<BATCH, THREADS>>>(x, Wp, weights, Wo, bo, (float*)d_out);
}

// round 7
// speedup vs baseline: 2.0205x; 1.3181x over previous
#include <cuda_runtime.h>
#include <cstdint>

#define NQ      12
#define DIM     4096      // 2^12 amplitudes
#define THREADS 256
#define BATCH   4096
#define FEAT    768
#define NCLASS  10

// ---- compile-time GF(2) composites of the fixed CNOT rings ----
__device__ __constant__ const int C0T[8] = {0x81F,0x83F,0x87F,0x8FF,0x9FF,0xBFF,0xFFF,0x7FF};
static __device__ __constant__ const int SLOTK0[16] = {
    0x000,0x801,0x803,0x002,0x807,0x006,0x004,0x805,
    0x80F,0x00E,0x00C,0x80D,0x008,0x809,0x80B,0x00A};
__device__ __constant__ const int C1T[8] = {0x401,0x802,0x405,0x80A,0x415,0x82A,0x455,0x8AA};
static __device__ __constant__ const int SLOTK1[16] = {
    0x000,0x550,0xAA0,0xFF0,0x150,0x400,0xBF0,0xEA0,
    0x2A0,0x7F0,0x800,0xD50,0x3F0,0x6A0,0x950,0xC00};
// layer-2 measurement masks -> Walsh coeffs {0,1,2,4,9} (unchanged from R5).

// ---- real RY gate sweep: 4 gates on local bits 0..3 (8 FMA per pair) ----
template <int STAGE>
__device__ __forceinline__ void apply4r(float2 amp[16], const float2 (&ry)[24], int lbase) {
#pragma unroll
    for (int g = 0; g < 4; ++g) {
        const int wire = 11 - (STAGE * 4 + g);
        const float2 m = ry[lbase + wire];
        const float c = m.x, s = m.y;
        const int mask = 1 << g;
#pragma unroll
        for (int k = 0; k < 8; ++k) {
            const int h  = ((k & ~(mask - 1)) << 1) | (k & (mask - 1));
            const int h2 = h | mask;
            const float2 a = amp[h], b2 = amp[h2];
            amp[h].x  = c * a.x - s * b2.x;
            amp[h].y  = c * a.y - s * b2.y;
            amp[h2].x = s * a.x + c * b2.x;
            amp[h2].y = s * a.y + c * b2.y;
        }
    }
}

// ---- product-diagonal application at a direct-index point ----
// angle(p) = base + sum_{set bits of t} angT[k] + (v part folded into Zv[v]).
__device__ __forceinline__ void apply_diag(float2 amp[16], const float2* Zv,
                                           const float* angT, int t) {
    float a = 0.f;
#pragma unroll
    for (int k = 0; k < 8; ++k) a += ((t >> k) & 1) ? angT[k] : 0.f;
    float zr, zi; __sincosf(a, &zi, &zr);
#pragma unroll
    for (int v = 0; v < 16; ++v) {
        const float2 z = Zv[v];                 // broadcast LDS
        const float wr = zr * z.x - zi * z.y;
        const float wi = zr * z.y + zi * z.x;
        const float nx = amp[v].x * wr - amp[v].y * wi;
        amp[v].y = amp[v].x * wi + amp[v].y * wr;
        amp[v].x = nx;
    }
}

__global__ __launch_bounds__(THREADS)
void qhead_kernel(const float* __restrict__ x,
                  const float* __restrict__ Wp,
                  const float* __restrict__ weights,
                  const float* __restrict__ Wo,
                  const float* __restrict__ bo,
                  float* __restrict__ out)
{
    __shared__ float2 st[DIM];          // swizzled state: slot(p) = p ^ ((p>>4)&15)
    __shared__ float2 cs[NQ];           // (cos(a/2), sin(a/2)) per wire
    __shared__ float  rot0[NQ][8];      // layer-0 Rot matrices (for init fold only)
    __shared__ float4 Fm[NQ];           // merged per-wire factor Rot0 * RY(a) |0>
    __shared__ float2 ry[24];           // (cos(th/2), sin(th/2)) for layers 1,2
    __shared__ float2 Zv[3][16];        // diagonal v-part tables (incl. base phase)
    __shared__ float  angT[3][8];       // diagonal t-part angles
    __shared__ float  red[8][NQ];       // cross-warp reduction buffer

    const int t    = threadIdx.x;
    const int b    = blockIdx.x;
    const int lane = t & 31;
    const int warp = t >> 5;

    // ---- angle encoding: 12 dot products (float4), tanh, half-angle sincos ----
    {
        const float4* xr4  = (const float4*)(x + (size_t)b * FEAT);
        const int q0 = warp;
        const bool two = (warp < 4);
        const float4* wp04 = (const float4*)(Wp + q0 * FEAT);
        const float4* wp14 = (const float4*)(Wp + (q0 + 8) * FEAT);
        float d0 = 0.f, d1 = 0.f;
#pragma unroll
        for (int i = lane; i < FEAT / 4; i += 32) {
            const float4 xv = xr4[i];
            const float4 a  = wp04[i];
            d0 += xv.x * a.x + xv.y * a.y + xv.z * a.z + xv.w * a.w;
            if (two) {
                const float4 c = wp14[i];
                d1 += xv.x * c.x + xv.y * c.y + xv.z * c.z + xv.w * c.w;
            }
        }
#pragma unroll
        for (int o = 16; o; o >>= 1) {
            d0 += __shfl_xor_sync(0xffffffffu, d0, o);
            d1 += __shfl_xor_sync(0xffffffffu, d1, o);
        }
        if (lane == 0) {
            float th = tanhf(d0) * 0.7853981633974483f;   // a/2
            float c, s; __sincosf(th, &s, &c);
            cs[q0] = make_float2(c, s);
            if (two) {
                float th1 = tanhf(d1) * 0.7853981633974483f;
                float c1, s1; __sincosf(th1, &s1, &c1);
                cs[q0 + 8] = make_float2(c1, s1);
            }
        }
    }

    // ---- layer-0 Rot matrices (full, for init fold) ----
    if (t < NQ) {
        const float phi = weights[t * 3 + 0];
        const float th  = weights[t * 3 + 1];
        const float om  = weights[t * 3 + 2];
        float c, s; __sincosf(0.5f * th, &s, &c);
        const float aa = 0.5f * (phi + om);
        const float bb = 0.5f * (phi - om);
        float sa, ca, sb, cb;
        __sincosf(aa, &sa, &ca);
        __sincosf(bb, &sb, &cb);
        rot0[t][0] =  c * ca;  rot0[t][1] = -c * sa;   // m00
        rot0[t][2] = -s * cb;  rot0[t][3] = -s * sb;   // m01
        rot0[t][4] =  s * cb;  rot0[t][5] = -s * sb;   // m10
        rot0[t][6] =  c * ca;  rot0[t][7] =  c * sa;   // m11
    }

    // ---- RY half-angle (c,s) for layers 1,2 ----
    if (t < 24) {
        const int l = 1 + t / 12, q = t % 12;
        const float th = weights[(l * 12 + q) * 3 + 1];
        float c, s; __sincosf(0.5f * th, &s, &c);
        ry[t] = make_float2(c, s);
    }

    // ---- diagonal tables: d=0 -> phi(layer1), d=1 -> omega(layer1), d=2 -> phi(layer2)
    //      angle(p) = -0.5*sum(ang) + sum_{set wires} ang_q.
    //      stage A (d=0,2): v bit m <-> wire 11-m, t bit k <-> wire 7-k
    //      stage C (d=1):   v bit m <-> wire 3-m,  t bit k <-> wire 11-k
    if (t < 48) {
        const int d = t >> 4, v = t & 15;
        const int l = (d == 2) ? 2 : 1;
        const int j = (d == 1) ? 2 : 0;
        float ang[12];
        float sum = 0.f;
#pragma unroll
        for (int q = 0; q < 12; ++q) { ang[q] = weights[(l * 12 + q) * 3 + j]; sum += ang[q]; }
        float a = -0.5f * sum;
#pragma unroll
        for (int m = 0; m < 4; ++m)
            if ((v >> m) & 1) a += (d == 1) ? ang[3 - m] : ang[11 - m];
        float zr, zi; __sincosf(a, &zi, &zr);
        Zv[d][v] = make_float2(zr, zi);
        if (v < 8) angT[d][v] = (d == 1) ? ang[11 - v] : ang[7 - v];
    }
    __syncthreads();

    // ---- merged per-wire factor: F = Rot0_q * (cos, sin)^T ----
    if (t < NQ) {
        const float c = cs[t].x, s = cs[t].y;
        const float* m = rot0[t];
        Fm[t] = make_float4(m[0] * c + m[2] * s,
                            m[1] * c + m[3] * s,
                            m[4] * c + m[6] * s,
                            m[5] * c + m[7] * s);
    }
    __syncthreads();

    // ---- init: post-layer0 product state scattered through layer-0 CNOT ring ----
    {
        float br, bi;
        {
            const float4 f = Fm[7];
            br = (t & 1) ? f.z : f.x;
            bi = (t & 1) ? f.w : f.y;
        }
#pragma unroll
        for (int k = 1; k < 8; ++k) {
            const float4 f = Fm[7 - k];
            const float fr = ((t >> k) & 1) ? f.z : f.x;
            const float fi = ((t >> k) & 1) ? f.w : f.y;
            const float nbr = br * fr - bi * fi;
            bi = br * fi + bi * fr;
            br = nbr;
        }
        float lr[4], li[4], hr[4], hi4[4];
        {
            const float4 fA = Fm[11], fB = Fm[10], fC = Fm[9], fD = Fm[8];
#pragma unroll
            for (int j = 0; j < 4; ++j) {
                const float ar = (j & 1) ? fA.z : fA.x, ai = (j & 1) ? fA.w : fA.y;
                const float br2 = (j & 2) ? fB.z : fB.x, bi2 = (j & 2) ? fB.w : fB.y;
                lr[j] = ar * br2 - ai * bi2;
                li[j] = ar * bi2 + ai * br2;
                const float cr = (j & 1) ? fC.z : fC.x, ci = (j & 1) ? fC.w : fC.y;
                const float dr = (j & 2) ? fD.z : fD.x, di = (j & 2) ? fD.w : fD.y;
                hr[j] = cr * dr - ci * di;
                hi4[j] = cr * di + ci * dr;
            }
        }
        int dT = 0;
#pragma unroll
        for (int k = 0; k < 8; ++k) dT ^= ((t >> k) & 1) ? C0T[k] : 0;
        const int sb0 = dT ^ ((dT >> 4) & 15);
#pragma unroll
        for (int v = 0; v < 16; ++v) {
            const float plr = lr[v & 3], pli = li[v & 3];
            const float phr = hr[v >> 2], phi2 = hi4[v >> 2];
            const float tr = plr * phr - pli * phi2;
            const float ti = plr * phi2 + pli * phr;
            st[sb0 ^ SLOTK0[v]] = make_float2(br * tr - bi * ti, br * ti + bi * tr);
        }
    }
    __syncthreads();

    float2 amp[16];

    // ===================== layer 1 =====================
    {   // stage A: p = t<<4 | v.  Dphi1 then RY wires 11..8
        const int base = t * 16, x4 = t & 15;
#pragma unroll
        for (int v = 0; v < 16; ++v) amp[v] = st[base + (v ^ x4)];
        apply_diag(amp, Zv[0], angT[0], t);
        apply4r<0>(amp, ry, 0);
#pragma unroll
        for (int v = 0; v < 16; ++v) st[base + (v ^ x4)] = amp[v];
    }
    __syncthreads();
    {   // stage B: RY wires 7..4
        const int hi = (t >> 4) * 256, x4 = t & 15;
#pragma unroll
        for (int v = 0; v < 16; ++v) amp[v] = st[hi + v * 16 + (x4 ^ v)];
        apply4r<1>(amp, ry, 0);
#pragma unroll
        for (int v = 0; v < 16; ++v) st[hi + v * 16 + (x4 ^ v)] = amp[v];
    }
    __syncthreads();
    {   // stage C: p = t | v<<8. RY wires 3..0, then Domega1, then C1 scatter
        const int slo = t ^ (t >> 4);
#pragma unroll
        for (int v = 0; v < 16; ++v) amp[v] = st[v * 256 + slo];
        apply4r<2>(amp, ry, 0);
        apply_diag(amp, Zv[1], angT[1], t);
        __syncthreads();
        int dT = 0;
#pragma unroll
        for (int j = 0; j < 8; ++j) dT ^= ((t >> j) & 1) ? C1T[j] : 0;
        const int sb1 = dT ^ ((dT >> 4) & 15);
#pragma unroll
        for (int v = 0; v < 16; ++v)
            st[sb1 ^ SLOTK1[v]] = amp[v];
        __syncthreads();
    }

    // ===================== layer 2 =====================
    {   // stage A: Dphi2 then RY wires 11..8
        const int base = t * 16, x4 = t & 15;
#pragma unroll
        for (int v = 0; v < 16; ++v) amp[v] = st[base + (v ^ x4)];
        apply_diag(amp, Zv[2], angT[2], t);
        apply4r<0>(amp, ry, 12);
#pragma unroll
        for (int v = 0; v < 16; ++v) st[base + (v ^ x4)] = amp[v];
    }
    __syncthreads();
    {   // stage B
        const int hi = (t >> 4) * 256, x4 = t & 15;
#pragma unroll
        for (int v = 0; v < 16; ++v) amp[v] = st[hi + v * 16 + (x4 ^ v)];
        apply4r<1>(amp, ry, 12);
#pragma unroll
        for (int v = 0; v < 16; ++v) st[hi + v * 16 + (x4 ^ v)] = amp[v];
    }
    __syncthreads();
    {   // stage C: RY wires 3..0; amps stay in regs (Domega2 dropped; C2 folded
        //          into measurement parity masks)
        const int slo = t ^ (t >> 4);
#pragma unroll
        for (int v = 0; v < 16; ++v) amp[v] = st[v * 256 + slo];
        apply4r<2>(amp, ry, 12);
    }

    // ---- PauliZ expectations via 5 Walsh coefficients of per-thread probs ----
    float pv[16];
#pragma unroll
    for (int v = 0; v < 16; ++v)
        pv[v] = amp[v].x * amp[v].x + amp[v].y * amp[v].y;

    const float Pe = ((pv[0] + pv[2]) + (pv[4] + pv[6])) + ((pv[8] + pv[10]) + (pv[12] + pv[14]));
    const float Po = ((pv[1] + pv[3]) + (pv[5] + pv[7])) + ((pv[9] + pv[11]) + (pv[13] + pv[15]));
    const float w0 = Pe + Po;
    const float w1 = Pe - Po;
    const float A  = ((pv[0] + pv[1]) + (pv[4] + pv[5])) + ((pv[8] + pv[9]) + (pv[12] + pv[13]));
    const float w2 = 2.f * A - w0;
    const float Bb = ((pv[0] + pv[1]) + (pv[2] + pv[3])) + ((pv[8] + pv[9]) + (pv[10] + pv[11]));
    const float w4 = 2.f * Bb - w0;
    const float Cc = ((pv[0] + pv[2]) + (pv[4] + pv[6])) + ((pv[9] + pv[11]) + (pv[13] + pv[15]));
    const float w9 = 2.f * Cc - w0;

    const int t0 = t & 1, t1 = (t >> 1) & 1, t2 = (t >> 2) & 1, t3 = (t >> 3) & 1;
    const int t4 = (t >> 4) & 1, t5 = (t >> 5) & 1, t6 = (t >> 6) & 1, t7 = (t >> 7) & 1;
    const int s24 = t2 ^ t5;
    const int s92 = t1 ^ t4 ^ t7;
    const int s49 = t0 ^ t3 ^ t6;
    const int s90 = t4 ^ t7;
    const int s48 = t3 ^ t6;

    float acc[NQ];
    acc[0]  = s24 ? -w1 : w1;
    acc[1]  = s92 ? -w0 : w0;
    acc[2]  = s49 ? -w0 : w0;
    acc[3]  = w9;
    acc[4]  = t7  ? -w4 : w4;
    acc[5]  = t6  ? -w2 : w2;
    acc[6]  = t5  ? -w9 : w9;
    acc[7]  = s90 ? -w4 : w4;
    acc[8]  = s48 ? -w2 : w2;
    acc[9]  = s24 ? -w9 : w9;
    acc[10] = s92 ? -w4 : w4;
    acc[11] = s49 ? -w2 : w2;

#pragma unroll
    for (int q = 0; q < NQ; ++q) {
        float vq = acc[q];
#pragma unroll
        for (int o = 16; o; o >>= 1) vq += __shfl_xor_sync(0xffffffffu, vq, o);
        if (lane == 0) red[warp][q] = vq;
    }
    __syncthreads();

    // ---- output head ----
    if (t < NCLASS) {
        float o = bo[t];
#pragma unroll
        for (int q = 0; q < NQ; ++q) {
            float z = 0.f;
#pragma unroll
            for (int w = 0; w < 8; ++w) z += red[w][q];
            o += z * Wo[t * NQ + q];
        }
        out[(size_t)b * NCLASS + t] = o;
    }
}

extern "C" void kernel_launch(void* const* d_in, const int* in_sizes, int n_in,
                              void* d_out, int out_size) {
    (void)in_sizes; (void)n_in; (void)out_size;
    const float* x       = (const float*)d_in[0];
    const float* Wp      = (const float*)d_in[1];
    const float* weights = (const float*)d_in[2];
    const float* Wo      = (const float*)d_in[3];
    const float* bo      = (const float*)d_in[4];

    qhead_kernel<<<BATCH, THREADS>>>(x, Wp, weights, Wo, bo, (float*)d_out);
}

// round 8
// speedup vs baseline: 2.0688x; 1.0239x over previous
#include <cuda_runtime.h>
#include <cstdint>

#define NQ      12
#define DIM     4096      // 2^12 amplitudes
#define THREADS 256
#define BATCH   4096
#define FEAT    768
#define NCLASS  10

// ---- compile-time GF(2) composites of the fixed CNOT rings ----
__device__ __constant__ const int C0T[8] = {0x81F,0x83F,0x87F,0x8FF,0x9FF,0xBFF,0xFFF,0x7FF};
static __device__ __constant__ const int SLOTK0[16] = {
    0x000,0x801,0x803,0x002,0x807,0x006,0x004,0x805,
    0x80F,0x00E,0x00C,0x80D,0x008,0x809,0x80B,0x00A};
__device__ __constant__ const int C1T[8] = {0x401,0x802,0x405,0x80A,0x415,0x82A,0x455,0x8AA};
static __device__ __constant__ const int SLOTK1[16] = {
    0x000,0x550,0xAA0,0xFF0,0x150,0x400,0xBF0,0xEA0,
    0x2A0,0x7F0,0x800,0xD50,0x3F0,0x6A0,0x950,0xC00};
// layer-2 measurement masks -> Walsh coeffs {0,1,2,4,9}.

// ---- real RY gate sweep: 4 gates on local bits 0..3 (8 FMA per pair) ----
template <int STAGE>
__device__ __forceinline__ void apply4r(float2 amp[16], const float2 (&ry)[24], int lbase) {
#pragma unroll
    for (int g = 0; g < 4; ++g) {
        const int wire = 11 - (STAGE * 4 + g);
        const float2 m = ry[lbase + wire];
        const float c = m.x, s = m.y;
        const int mask = 1 << g;
#pragma unroll
        for (int k = 0; k < 8; ++k) {
            const int h  = ((k & ~(mask - 1)) << 1) | (k & (mask - 1));
            const int h2 = h | mask;
            const float2 a = amp[h], b2 = amp[h2];
            amp[h].x  = c * a.x - s * b2.x;
            amp[h].y  = c * a.y - s * b2.y;
            amp[h2].x = s * a.x + c * b2.x;
            amp[h2].y = s * a.y + c * b2.y;
        }
    }
}

// ---- product-diagonal application at a direct-index point ----
__device__ __forceinline__ void apply_diag(float2 amp[16], const float2* Zv,
                                           const float* angT, int t) {
    float a = 0.f;
#pragma unroll
    for (int k = 0; k < 8; ++k) a += ((t >> k) & 1) ? angT[k] : 0.f;
    float zr, zi; __sincosf(a, &zi, &zr);
#pragma unroll
    for (int v = 0; v < 16; ++v) {
        const float2 z = Zv[v];                 // broadcast LDS
        const float wr = zr * z.x - zi * z.y;
        const float wi = zr * z.y + zi * z.x;
        const float nx = amp[v].x * wr - amp[v].y * wi;
        amp[v].y = amp[v].x * wi + amp[v].y * wr;
        amp[v].x = nx;
    }
}

__global__ __launch_bounds__(THREADS, 3)
void qhead_kernel(const float* __restrict__ x,
                  const float* __restrict__ Wp,
                  const float* __restrict__ weights,
                  const float* __restrict__ Wo,
                  const float* __restrict__ bo,
                  float* __restrict__ out)
{
    __shared__ float2 st[DIM];          // swizzled state: slot(p) = p ^ ((p>>4)&15)
    __shared__ float2 cs[NQ];           // (cos(a/2), sin(a/2)) per wire
    __shared__ float  rot0[NQ][8];      // layer-0 Rot matrices (for init fold only)
    __shared__ float4 Fm[NQ];           // merged per-wire factor Rot0 * RY(a) |0>
    __shared__ float2 ry[24];           // (cos(th/2), sin(th/2)) for layers 1,2
    __shared__ float2 Zv[3][16];        // diagonal v-part tables (incl. base phase)
    __shared__ float  angT[3][8];       // diagonal t-part angles
    __shared__ float  red[8][NQ];       // cross-warp reduction buffer

    const int t    = threadIdx.x;
    const int b    = blockIdx.x;
    const int lane = t & 31;
    const int warp = t >> 5;

    // ---- angle encoding: 12 dot products (float4), tanh, half-angle sincos ----
    {
        const float4* xr4  = (const float4*)(x + (size_t)b * FEAT);
        const int q0 = warp;
        const bool two = (warp < 4);
        const float4* wp04 = (const float4*)(Wp + q0 * FEAT);
        const float4* wp14 = (const float4*)(Wp + (q0 + 8) * FEAT);
        float d0 = 0.f, d1 = 0.f;
#pragma unroll
        for (int i = lane; i < FEAT / 4; i += 32) {
            const float4 xv = xr4[i];
            const float4 a  = wp04[i];
            d0 += xv.x * a.x + xv.y * a.y + xv.z * a.z + xv.w * a.w;
            if (two) {
                const float4 c = wp14[i];
                d1 += xv.x * c.x + xv.y * c.y + xv.z * c.z + xv.w * c.w;
            }
        }
#pragma unroll
        for (int o = 16; o; o >>= 1) {
            d0 += __shfl_xor_sync(0xffffffffu, d0, o);
            d1 += __shfl_xor_sync(0xffffffffu, d1, o);
        }
        if (lane == 0) {
            float th = tanhf(d0) * 0.7853981633974483f;   // a/2
            float c, s; __sincosf(th, &s, &c);
            cs[q0] = make_float2(c, s);
            if (two) {
                float th1 = tanhf(d1) * 0.7853981633974483f;
                float c1, s1; __sincosf(th1, &s1, &c1);
                cs[q0 + 8] = make_float2(c1, s1);
            }
        }
    }

    // ---- layer-0 Rot matrices (full, for init fold) ----
    if (t < NQ) {
        const float phi = weights[t * 3 + 0];
        const float th  = weights[t * 3 + 1];
        const float om  = weights[t * 3 + 2];
        float c, s; __sincosf(0.5f * th, &s, &c);
        const float aa = 0.5f * (phi + om);
        const float bb = 0.5f * (phi - om);
        float sa, ca, sb, cb;
        __sincosf(aa, &sa, &ca);
        __sincosf(bb, &sb, &cb);
        rot0[t][0] =  c * ca;  rot0[t][1] = -c * sa;   // m00
        rot0[t][2] = -s * cb;  rot0[t][3] = -s * sb;   // m01
        rot0[t][4] =  s * cb;  rot0[t][5] = -s * sb;   // m10
        rot0[t][6] =  c * ca;  rot0[t][7] =  c * sa;   // m11
    }

    // ---- RY half-angle (c,s) for layers 1,2 ----
    if (t < 24) {
        const int l = 1 + t / 12, q = t % 12;
        const float th = weights[(l * 12 + q) * 3 + 1];
        float c, s; __sincosf(0.5f * th, &s, &c);
        ry[t] = make_float2(c, s);
    }

    // ---- diagonal tables: d=0 -> phi(l1), d=1 -> omega(l1), d=2 -> phi(l2) ----
    if (t < 48) {
        const int d = t >> 4, v = t & 15;
        const int l = (d == 2) ? 2 : 1;
        const int j = (d == 1) ? 2 : 0;
        float ang[12];
        float sum = 0.f;
#pragma unroll
        for (int q = 0; q < 12; ++q) { ang[q] = weights[(l * 12 + q) * 3 + j]; sum += ang[q]; }
        float a = -0.5f * sum;
#pragma unroll
        for (int m = 0; m < 4; ++m)
            if ((v >> m) & 1) a += (d == 1) ? ang[3 - m] : ang[11 - m];
        float zr, zi; __sincosf(a, &zi, &zr);
        Zv[d][v] = make_float2(zr, zi);
        if (v < 8) angT[d][v] = (d == 1) ? ang[11 - v] : ang[7 - v];
    }
    __syncthreads();

    // ---- merged per-wire factor: F = Rot0_q * (cos, sin)^T ----
    if (t < NQ) {
        const float c = cs[t].x, s = cs[t].y;
        const float* m = rot0[t];
        Fm[t] = make_float4(m[0] * c + m[2] * s,
                            m[1] * c + m[3] * s,
                            m[4] * c + m[6] * s,
                            m[5] * c + m[7] * s);
    }
    __syncthreads();

    // ---- init: post-layer0 product state scattered through layer-0 CNOT ring ----
    {
        float br, bi;
        {
            const float4 f = Fm[7];
            br = (t & 1) ? f.z : f.x;
            bi = (t & 1) ? f.w : f.y;
        }
#pragma unroll
        for (int k = 1; k < 8; ++k) {
            const float4 f = Fm[7 - k];
            const float fr = ((t >> k) & 1) ? f.z : f.x;
            const float fi = ((t >> k) & 1) ? f.w : f.y;
            const float nbr = br * fr - bi * fi;
            bi = br * fi + bi * fr;
            br = nbr;
        }
        float lr[4], li[4], hr[4], hi4[4];
        {
            const float4 fA = Fm[11], fB = Fm[10], fC = Fm[9], fD = Fm[8];
#pragma unroll
            for (int j = 0; j < 4; ++j) {
                const float ar = (j & 1) ? fA.z : fA.x, ai = (j & 1) ? fA.w : fA.y;
                const float br2 = (j & 2) ? fB.z : fB.x, bi2 = (j & 2) ? fB.w : fB.y;
                lr[j] = ar * br2 - ai * bi2;
                li[j] = ar * bi2 + ai * br2;
                const float cr = (j & 1) ? fC.z : fC.x, ci = (j & 1) ? fC.w : fC.y;
                const float dr = (j & 2) ? fD.z : fD.x, di = (j & 2) ? fD.w : fD.y;
                hr[j] = cr * dr - ci * di;
                hi4[j] = cr * di + ci * dr;
            }
        }
        int dT = 0;
#pragma unroll
        for (int k = 0; k < 8; ++k) dT ^= ((t >> k) & 1) ? C0T[k] : 0;
        const int sb0 = dT ^ ((dT >> 4) & 15);
#pragma unroll
        for (int v = 0; v < 16; ++v) {
            const float plr = lr[v & 3], pli = li[v & 3];
            const float phr = hr[v >> 2], phi2 = hi4[v >> 2];
            const float tr = plr * phr - pli * phi2;
            const float ti = plr * phi2 + pli * phr;
            st[sb0 ^ SLOTK0[v]] = make_float2(br * tr - bi * ti, br * ti + bi * tr);
        }
    }
    __syncthreads();

    float2 amp[16];

    // ===================== layer 1 =====================
    {   // stage A: p = t<<4 | v.  Dphi1 then RY wires 11..8
        const int base = t * 16, x4 = t & 15;
#pragma unroll
        for (int v = 0; v < 16; ++v) amp[v] = st[base + (v ^ x4)];
        apply_diag(amp, Zv[0], angT[0], t);
        apply4r<0>(amp, ry, 0);
#pragma unroll
        for (int v = 0; v < 16; ++v) st[base + (v ^ x4)] = amp[v];
    }
    __syncthreads();
    {   // stage B: RY wires 7..4
        const int hi = (t >> 4) * 256, x4 = t & 15;
#pragma unroll
        for (int v = 0; v < 16; ++v) amp[v] = st[hi + v * 16 + (x4 ^ v)];
        apply4r<1>(amp, ry, 0);
#pragma unroll
        for (int v = 0; v < 16; ++v) st[hi + v * 16 + (x4 ^ v)] = amp[v];
    }
    __syncthreads();
    {   // stage C: p = t | v<<8. RY wires 3..0, then Domega1, then C1 scatter
        const int slo = t ^ (t >> 4);
#pragma unroll
        for (int v = 0; v < 16; ++v) amp[v] = st[v * 256 + slo];
        apply4r<2>(amp, ry, 0);
        apply_diag(amp, Zv[1], angT[1], t);
        __syncthreads();
        int dT = 0;
#pragma unroll
        for (int j = 0; j < 8; ++j) dT ^= ((t >> j) & 1) ? C1T[j] : 0;
        const int sb1 = dT ^ ((dT >> 4) & 15);
#pragma unroll
        for (int v = 0; v < 16; ++v)
            st[sb1 ^ SLOTK1[v]] = amp[v];
        __syncthreads();
    }

    // ===================== layer 2 =====================
    {   // stage A: Dphi2 then RY wires 11..8
        const int base = t * 16, x4 = t & 15;
#pragma unroll
        for (int v = 0; v < 16; ++v) amp[v] = st[base + (v ^ x4)];
        apply_diag(amp, Zv[2], angT[2], t);
        apply4r<0>(amp, ry, 12);
#pragma unroll
        for (int v = 0; v < 16; ++v) st[base + (v ^ x4)] = amp[v];
    }
    __syncthreads();
    {   // stage B
        const int hi = (t >> 4) * 256, x4 = t & 15;
#pragma unroll
        for (int v = 0; v < 16; ++v) amp[v] = st[hi + v * 16 + (x4 ^ v)];
        apply4r<1>(amp, ry, 12);
#pragma unroll
        for (int v = 0; v < 16; ++v) st[hi + v * 16 + (x4 ^ v)] = amp[v];
    }
    __syncthreads();
    {   // stage C: RY wires 3..0; amps stay in regs (Domega2 dropped; C2 folded
        //          into measurement parity masks)
        const int slo = t ^ (t >> 4);
#pragma unroll
        for (int v = 0; v < 16; ++v) amp[v] = st[v * 256 + slo];
        apply4r<2>(amp, ry, 12);
    }

    // ---- probs in place (frees the old pv[16] registers) ----
#pragma unroll
    for (int v = 0; v < 16; ++v)
        amp[v].x = amp[v].x * amp[v].x + amp[v].y * amp[v].y;

    // ---- PauliZ expectations via 5 Walsh coefficients of per-thread probs ----
    const float Pe = ((amp[0].x + amp[2].x) + (amp[4].x + amp[6].x))
                   + ((amp[8].x + amp[10].x) + (amp[12].x + amp[14].x));
    const float Po = ((amp[1].x + amp[3].x) + (amp[5].x + amp[7].x))
                   + ((amp[9].x + amp[11].x) + (amp[13].x + amp[15].x));
    const float w0 = Pe + Po;
    const float w1 = Pe - Po;
    const float A  = ((amp[0].x + amp[1].x) + (amp[4].x + amp[5].x))
                   + ((amp[8].x + amp[9].x) + (amp[12].x + amp[13].x));
    const float w2 = 2.f * A - w0;
    const float Bb = ((amp[0].x + amp[1].x) + (amp[2].x + amp[3].x))
                   + ((amp[8].x + amp[9].x) + (amp[10].x + amp[11].x));
    const float w4 = 2.f * Bb - w0;
    const float Cc = ((amp[0].x + amp[2].x) + (amp[4].x + amp[6].x))
                   + ((amp[9].x + amp[11].x) + (amp[13].x + amp[15].x));
    const float w9 = 2.f * Cc - w0;

    const int t0 = t & 1, t1 = (t >> 1) & 1, t2 = (t >> 2) & 1, t3 = (t >> 3) & 1;
    const int t4 = (t >> 4) & 1, t5 = (t >> 5) & 1, t6 = (t >> 6) & 1, t7 = (t >> 7) & 1;
    const int s24 = t2 ^ t5;
    const int s92 = t1 ^ t4 ^ t7;
    const int s49 = t0 ^ t3 ^ t6;
    const int s90 = t4 ^ t7;
    const int s48 = t3 ^ t6;

    float acc[NQ];
    acc[0]  = s24 ? -w1 : w1;
    acc[1]  = s92 ? -w0 : w0;
    acc[2]  = s49 ? -w0 : w0;
    acc[3]  = w9;
    acc[4]  = t7  ? -w4 : w4;
    acc[5]  = t6  ? -w2 : w2;
    acc[6]  = t5  ? -w9 : w9;
    acc[7]  = s90 ? -w4 : w4;
    acc[8]  = s48 ? -w2 : w2;
    acc[9]  = s24 ? -w9 : w9;
    acc[10] = s92 ? -w4 : w4;
    acc[11] = s49 ? -w2 : w2;

#pragma unroll
    for (int q = 0; q < NQ; ++q) {
        float vq = acc[q];
#pragma unroll
        for (int o = 16; o; o >>= 1) vq += __shfl_xor_sync(0xffffffffu, vq, o);
        if (lane == 0) red[warp][q] = vq;
    }
    __syncthreads();

    // ---- output head ----
    if (t < NCLASS) {
        float o = bo[t];
#pragma unroll
        for (int q = 0; q < NQ; ++q) {
            float z = 0.f;
#pragma unroll
            for (int w = 0; w < 8; ++w) z += red[w][q];
            o += z * Wo[t * NQ + q];
        }
        out[(size_t)b * NCLASS + t] = o;
    }
}

extern "C" void kernel_launch(void* const* d_in, const int* in_sizes, int n_in,
                              void* d_out, int out_size) {
    (void)in_sizes; (void)n_in; (void)out_size;
    const float* x       = (const float*)d_in[0];
    const float* Wp      = (const float*)d_in[1];
    const float* weights = (const float*)d_in[2];
    const float* Wo      = (const float*)d_in[3];
    const float* bo      = (const float*)d_in[4];

    qhead_kernel<<<BATCH, THREADS>>>(x, Wp, weights, Wo, bo, (float*)d_out);
}